// round 2
// baseline (speedup 1.0000x reference)
#include <cuda_runtime.h>

// Problem constants (fixed shapes from reference setup_inputs)
#define T_STEPS 4
#define B_BATCH 32            // TB / T = 128/4
#define N_SEQ   1024
#define CIN     512
#define COUT    512
#define M_TOTAL (T_STEPS * B_BATCH * N_SEQ)   // 131072 rows

// Scratch in device globals (no allocations allowed)
__device__ float g_y[(size_t)M_TOTAL * COUT];      // 268 MB GEMM output
#define NPART 1024                                  // one partial per M-tile
__device__ float g_psum[NPART * COUT];
__device__ float g_psq [NPART * COUT];
__device__ float g_mean[COUT];
__device__ float g_rstd[COUT];

// ---------------------------------------------------------------------------
// SGEMM: C[m,o] = sum_k A[m,k] * W[o,k]
// 128x128x16 tile, 256 threads, 8x8 per thread (4+4 clustered rows/cols),
// double-buffered smem with register-staged global prefetch.
// Epilogue additionally produces per-(M-tile, channel) partial sums/sumsq
// for BatchNorm statistics (deterministic tree reduction).
// ---------------------------------------------------------------------------
#define BM 128
#define BNb 128
#define BK 16
#define SPAD 4

__global__ void __launch_bounds__(256)
gemm_k(const float* __restrict__ A, const float* __restrict__ W) {
    __shared__ float As[2][BK][BM + SPAD];
    __shared__ float Ws[2][BK][BNb + SPAD];

    const int tid = threadIdx.x;
    const int tx = tid & 15;       // 0..15
    const int ty = tid >> 4;       // 0..15
    const int m0 = blockIdx.y * BM;
    const int n0 = blockIdx.x * BNb;

    // thread-owned rows: ar0+{0..3} and 64+ar0+{0..3}; cols likewise
    const int ar0 = ty * 4;
    const int bc0 = tx * 4;

    // global load indices (per stage: 2 float4 for A, 2 for W)
    const int lrow0 = tid >> 2;          // 0..63
    const int lrow1 = lrow0 + 64;        // 64..127
    const int lkv   = (tid & 3) * 4;     // 0,4,8,12

    const float* Aptr0 = A + (size_t)(m0 + lrow0) * CIN + lkv;
    const float* Aptr1 = A + (size_t)(m0 + lrow1) * CIN + lkv;
    const float* Wptr0 = W + (size_t)(n0 + lrow0) * CIN + lkv;
    const float* Wptr1 = W + (size_t)(n0 + lrow1) * CIN + lkv;

    float acc[8][8];
#pragma unroll
    for (int i = 0; i < 8; i++)
#pragma unroll
        for (int j = 0; j < 8; j++) acc[i][j] = 0.0f;

    // ---- prologue: load stage 0 into smem buffer 0
    {
        float4 ra0 = *reinterpret_cast<const float4*>(Aptr0);
        float4 ra1 = *reinterpret_cast<const float4*>(Aptr1);
        float4 rw0 = *reinterpret_cast<const float4*>(Wptr0);
        float4 rw1 = *reinterpret_cast<const float4*>(Wptr1);
        As[0][lkv + 0][lrow0] = ra0.x; As[0][lkv + 1][lrow0] = ra0.y;
        As[0][lkv + 2][lrow0] = ra0.z; As[0][lkv + 3][lrow0] = ra0.w;
        As[0][lkv + 0][lrow1] = ra1.x; As[0][lkv + 1][lrow1] = ra1.y;
        As[0][lkv + 2][lrow1] = ra1.z; As[0][lkv + 3][lrow1] = ra1.w;
        Ws[0][lkv + 0][lrow0] = rw0.x; Ws[0][lkv + 1][lrow0] = rw0.y;
        Ws[0][lkv + 2][lrow0] = rw0.z; Ws[0][lkv + 3][lrow0] = rw0.w;
        Ws[0][lkv + 0][lrow1] = rw1.x; Ws[0][lkv + 1][lrow1] = rw1.y;
        Ws[0][lkv + 2][lrow1] = rw1.z; Ws[0][lkv + 3][lrow1] = rw1.w;
    }
    __syncthreads();

    const int NSTAGE = CIN / BK;   // 32
    float4 ra0, ra1, rw0, rw1;

#pragma unroll 1
    for (int s = 0; s < NSTAGE; s++) {
        const int cur = s & 1;
        const int nxt = cur ^ 1;

        // issue global loads for next stage (latency hidden by compute)
        if (s + 1 < NSTAGE) {
            const int koff = (s + 1) * BK;
            ra0 = *reinterpret_cast<const float4*>(Aptr0 + koff);
            ra1 = *reinterpret_cast<const float4*>(Aptr1 + koff);
            rw0 = *reinterpret_cast<const float4*>(Wptr0 + koff);
            rw1 = *reinterpret_cast<const float4*>(Wptr1 + koff);
        }

        // compute current stage
#pragma unroll
        for (int kk = 0; kk < BK; kk++) {
            float4 a0 = *reinterpret_cast<const float4*>(&As[cur][kk][ar0]);
            float4 a1 = *reinterpret_cast<const float4*>(&As[cur][kk][ar0 + 64]);
            float4 b0 = *reinterpret_cast<const float4*>(&Ws[cur][kk][bc0]);
            float4 b1 = *reinterpret_cast<const float4*>(&Ws[cur][kk][bc0 + 64]);
            float a[8] = {a0.x, a0.y, a0.z, a0.w, a1.x, a1.y, a1.z, a1.w};
            float b[8] = {b0.x, b0.y, b0.z, b0.w, b1.x, b1.y, b1.z, b1.w};
#pragma unroll
            for (int i = 0; i < 8; i++)
#pragma unroll
                for (int j = 0; j < 8; j++)
                    acc[i][j] = fmaf(a[i], b[j], acc[i][j]);
        }

        // stage next buffer
        if (s + 1 < NSTAGE) {
            As[nxt][lkv + 0][lrow0] = ra0.x; As[nxt][lkv + 1][lrow0] = ra0.y;
            As[nxt][lkv + 2][lrow0] = ra0.z; As[nxt][lkv + 3][lrow0] = ra0.w;
            As[nxt][lkv + 0][lrow1] = ra1.x; As[nxt][lkv + 1][lrow1] = ra1.y;
            As[nxt][lkv + 2][lrow1] = ra1.z; As[nxt][lkv + 3][lrow1] = ra1.w;
            Ws[nxt][lkv + 0][lrow0] = rw0.x; Ws[nxt][lkv + 1][lrow0] = rw0.y;
            Ws[nxt][lkv + 2][lrow0] = rw0.z; Ws[nxt][lkv + 3][lrow0] = rw0.w;
            Ws[nxt][lkv + 0][lrow1] = rw1.x; Ws[nxt][lkv + 1][lrow1] = rw1.y;
            Ws[nxt][lkv + 2][lrow1] = rw1.z; Ws[nxt][lkv + 3][lrow1] = rw1.w;
            __syncthreads();
        }
    }

    // ---- store C tile (float4 per 4-col cluster)
#pragma unroll
    for (int ih = 0; ih < 2; ih++) {
#pragma unroll
        for (int i = 0; i < 4; i++) {
            const size_t m = (size_t)(m0 + ih * 64 + ar0 + i);
            const int ia = ih * 4 + i;
            float4 v0 = make_float4(acc[ia][0], acc[ia][1], acc[ia][2], acc[ia][3]);
            float4 v1 = make_float4(acc[ia][4], acc[ia][5], acc[ia][6], acc[ia][7]);
            *reinterpret_cast<float4*>(&g_y[m * COUT + n0 + bc0])      = v0;
            *reinterpret_cast<float4*>(&g_y[m * COUT + n0 + 64 + bc0]) = v1;
        }
    }

    // ---- fused BN partial stats for this (M-tile, 128 channels)
    // Per-thread: sum over its 8 rows for each of its 8 cols.
    __syncthreads();   // done reading As/Ws smem; safe to reuse
    float* sred = &As[0][0][0];   // [16][128] = 2048 floats (fits in As)
    float* qred = &Ws[0][0][0];   // [16][128]

    float s8[8], q8[8];
#pragma unroll
    for (int j = 0; j < 8; j++) { s8[j] = 0.0f; q8[j] = 0.0f; }
#pragma unroll
    for (int i = 0; i < 8; i++)
#pragma unroll
        for (int j = 0; j < 8; j++) {
            float v = acc[i][j];
            s8[j] += v;
            q8[j] = fmaf(v, v, q8[j]);
        }
#pragma unroll
    for (int jh = 0; jh < 2; jh++)
#pragma unroll
        for (int j = 0; j < 4; j++) {
            int c = jh * 64 + bc0 + j;         // CTA-local col 0..127
            sred[ty * 128 + c] = s8[jh * 4 + j];
            qred[ty * 128 + c] = q8[jh * 4 + j];
        }
    __syncthreads();

    if (tid < 128) {
        float s = 0.0f, q = 0.0f;
#pragma unroll
        for (int k = 0; k < 16; k++) {
            s += sred[k * 128 + tid];
            q += qred[k * 128 + tid];
        }
        g_psum[(size_t)blockIdx.y * COUT + n0 + tid] = s;
        g_psq [(size_t)blockIdx.y * COUT + n0 + tid] = q;
    }
}

// Finalize mean / rstd per channel (1 block, 512 threads)
__global__ void __launch_bounds__(COUT)
stats2_k() {
    const int o = threadIdx.x;
    float s = 0.0f, sq = 0.0f;
    for (int i = 0; i < NPART; i++) {
        s  += g_psum[i * COUT + o];
        sq += g_psq [i * COUT + o];
    }
    const float inv_m = 1.0f / (float)M_TOTAL;
    float mean = s * inv_m;
    float var  = sq * inv_m - mean * mean;
    g_mean[o] = mean;
    g_rstd[o] = rsqrtf(var + 1e-5f);
}

// ---------------------------------------------------------------------------
// Fused BN + multistep LIF + output store (HBM-bound; unchanged).
// ---------------------------------------------------------------------------
__global__ void __launch_bounds__(256)
lif_k(const float* __restrict__ gamma, const float* __restrict__ beta,
      float* __restrict__ out) {
    const int idx = blockIdx.x * blockDim.x + threadIdx.x;  // (b*N+n)*COUT + o
    const int total = B_BATCH * N_SEQ * COUT;
    if (idx >= total) return;
    const int o = idx & (COUT - 1);

    const float mean = g_mean[o];
    const float rstd = g_rstd[o];
    const float ga = gamma[o];
    const float be = beta[o];

    const size_t stride = (size_t)B_BATCH * N_SEQ * COUT;   // per-timestep stride
    const size_t base = (size_t)idx;

    float v = 0.0f;
#pragma unroll
    for (int t = 0; t < T_STEPS; t++) {
        const size_t off = base + (size_t)t * stride;
        float raw = g_y[off];
        float xt = (raw - mean) * rstd;
        xt = xt * ga + be;
        float d = xt - v;
        v = v + d * 0.5f;
        float sp = (v >= 1.0f) ? 1.0f : 0.0f;
        out[off] = sp;
        v = v * (1.0f - sp);
    }
}

// ---------------------------------------------------------------------------
extern "C" void kernel_launch(void* const* d_in, const int* in_sizes, int n_in,
                              void* d_out, int out_size) {
    const float* x     = (const float*)d_in[0];  // [TB, N, Cin] = [M_TOTAL, CIN]
    const float* W     = (const float*)d_in[1];  // [COUT, CIN]
    const float* gamma = (const float*)d_in[2];
    const float* beta  = (const float*)d_in[3];
    float* out = (float*)d_out;

    dim3 gemm_grid(COUT / BNb, M_TOTAL / BM);    // (4, 1024)
    gemm_k<<<gemm_grid, 256>>>(x, W);

    stats2_k<<<1, COUT>>>();

    const int total = B_BATCH * N_SEQ * COUT;    // 16.7M elements
    lif_k<<<(total + 255) / 256, 256>>>(gamma, beta, out);
}

// round 3
// speedup vs baseline: 1.2378x; 1.2378x over previous
#include <cuda_runtime.h>

// Problem constants (fixed shapes from reference setup_inputs)
#define T_STEPS 4
#define B_BATCH 32            // TB / T = 128/4
#define N_SEQ   1024
#define CIN     512
#define COUT    512
#define M_TOTAL (T_STEPS * B_BATCH * N_SEQ)   // 131072 rows

// Scratch in device globals (no allocations allowed)
__device__ float g_y[(size_t)M_TOTAL * COUT];      // 268 MB GEMM output
#define NPART 1024                                  // one partial per M-tile
__device__ float g_psum[NPART * COUT];
__device__ float g_psq [NPART * COUT];
__device__ float g_mean[COUT];
__device__ float g_rstd[COUT];

// ---------------------------------------------------------------------------
// SGEMM: C[m,o] = sum_k A[m,k] * W[o,k]
// 128x128x16 tile, 256 threads, 8x8 per thread (4+4 clustered rows/cols),
// double-buffered smem with register-staged global prefetch.
// __launch_bounds__(256, 2) caps regs at 128 -> 2 CTAs/SM (the r2 kernel hit
// 129 regs -> 1 CTA/SM -> occupancy collapse).
// Epilogue additionally produces per-(M-tile, channel) partial sums/sumsq
// for BatchNorm statistics (deterministic tree reduction).
// ---------------------------------------------------------------------------
#define BM 128
#define BNb 128
#define BK 16
#define SPAD 4

__global__ void __launch_bounds__(256, 2)
gemm_k(const float* __restrict__ A, const float* __restrict__ W) {
    __shared__ float As[2][BK][BM + SPAD];
    __shared__ float Ws[2][BK][BNb + SPAD];

    const int tid = threadIdx.x;
    const int tx = tid & 15;       // 0..15
    const int ty = tid >> 4;       // 0..15
    const int m0 = blockIdx.y * BM;
    const int n0 = blockIdx.x * BNb;

    // thread-owned rows: ar0+{0..3} and 64+ar0+{0..3}; cols likewise
    const int ar0 = ty * 4;
    const int bc0 = tx * 4;

    // global load indices (per stage: 2 float4 for A, 2 for W)
    const int lrow0 = tid >> 2;          // 0..63
    const int lkv   = (tid & 3) * 4;     // 0,4,8,12

    const float* Aptr0 = A + (size_t)(m0 + lrow0) * CIN + lkv;
    const float* Wptr0 = W + (size_t)(n0 + lrow0) * CIN + lkv;
    const size_t row64 = (size_t)64 * CIN;

    float acc[8][8];
#pragma unroll
    for (int i = 0; i < 8; i++)
#pragma unroll
        for (int j = 0; j < 8; j++) acc[i][j] = 0.0f;

    // ---- prologue: load stage 0 into smem buffer 0
    {
        float4 ra0 = *reinterpret_cast<const float4*>(Aptr0);
        float4 ra1 = *reinterpret_cast<const float4*>(Aptr0 + row64);
        float4 rw0 = *reinterpret_cast<const float4*>(Wptr0);
        float4 rw1 = *reinterpret_cast<const float4*>(Wptr0 + row64);
        As[0][lkv + 0][lrow0] = ra0.x; As[0][lkv + 1][lrow0] = ra0.y;
        As[0][lkv + 2][lrow0] = ra0.z; As[0][lkv + 3][lrow0] = ra0.w;
        As[0][lkv + 0][lrow0 + 64] = ra1.x; As[0][lkv + 1][lrow0 + 64] = ra1.y;
        As[0][lkv + 2][lrow0 + 64] = ra1.z; As[0][lkv + 3][lrow0 + 64] = ra1.w;
        Ws[0][lkv + 0][lrow0] = rw0.x; Ws[0][lkv + 1][lrow0] = rw0.y;
        Ws[0][lkv + 2][lrow0] = rw0.z; Ws[0][lkv + 3][lrow0] = rw0.w;
        Ws[0][lkv + 0][lrow0 + 64] = rw1.x; Ws[0][lkv + 1][lrow0 + 64] = rw1.y;
        Ws[0][lkv + 2][lrow0 + 64] = rw1.z; Ws[0][lkv + 3][lrow0 + 64] = rw1.w;
    }
    __syncthreads();

    const int NSTAGE = CIN / BK;   // 32
    float4 ra0, ra1, rw0, rw1;

#pragma unroll 1
    for (int s = 0; s < NSTAGE; s++) {
        const int cur = s & 1;
        const int nxt = cur ^ 1;

        // issue global loads for next stage (latency hidden by compute)
        if (s + 1 < NSTAGE) {
            const int koff = (s + 1) * BK;
            ra0 = *reinterpret_cast<const float4*>(Aptr0 + koff);
            ra1 = *reinterpret_cast<const float4*>(Aptr0 + row64 + koff);
            rw0 = *reinterpret_cast<const float4*>(Wptr0 + koff);
            rw1 = *reinterpret_cast<const float4*>(Wptr0 + row64 + koff);
        }

        // compute current stage
#pragma unroll
        for (int kk = 0; kk < BK; kk++) {
            float4 a0 = *reinterpret_cast<const float4*>(&As[cur][kk][ar0]);
            float4 a1 = *reinterpret_cast<const float4*>(&As[cur][kk][ar0 + 64]);
            float4 b0 = *reinterpret_cast<const float4*>(&Ws[cur][kk][bc0]);
            float4 b1 = *reinterpret_cast<const float4*>(&Ws[cur][kk][bc0 + 64]);
            float a[8] = {a0.x, a0.y, a0.z, a0.w, a1.x, a1.y, a1.z, a1.w};
            float b[8] = {b0.x, b0.y, b0.z, b0.w, b1.x, b1.y, b1.z, b1.w};
#pragma unroll
            for (int i = 0; i < 8; i++)
#pragma unroll
                for (int j = 0; j < 8; j++)
                    acc[i][j] = fmaf(a[i], b[j], acc[i][j]);
        }

        // stage next buffer
        if (s + 1 < NSTAGE) {
            As[nxt][lkv + 0][lrow0] = ra0.x; As[nxt][lkv + 1][lrow0] = ra0.y;
            As[nxt][lkv + 2][lrow0] = ra0.z; As[nxt][lkv + 3][lrow0] = ra0.w;
            As[nxt][lkv + 0][lrow0 + 64] = ra1.x; As[nxt][lkv + 1][lrow0 + 64] = ra1.y;
            As[nxt][lkv + 2][lrow0 + 64] = ra1.z; As[nxt][lkv + 3][lrow0 + 64] = ra1.w;
            Ws[nxt][lkv + 0][lrow0] = rw0.x; Ws[nxt][lkv + 1][lrow0] = rw0.y;
            Ws[nxt][lkv + 2][lrow0] = rw0.z; Ws[nxt][lkv + 3][lrow0] = rw0.w;
            Ws[nxt][lkv + 0][lrow0 + 64] = rw1.x; Ws[nxt][lkv + 1][lrow0 + 64] = rw1.y;
            Ws[nxt][lkv + 2][lrow0 + 64] = rw1.z; Ws[nxt][lkv + 3][lrow0 + 64] = rw1.w;
            __syncthreads();
        }
    }

    // ---- store C tile (float4 per 4-col cluster)
#pragma unroll
    for (int ih = 0; ih < 2; ih++) {
#pragma unroll
        for (int i = 0; i < 4; i++) {
            const size_t m = (size_t)(m0 + ih * 64 + ar0 + i);
            const int ia = ih * 4 + i;
            float4 v0 = make_float4(acc[ia][0], acc[ia][1], acc[ia][2], acc[ia][3]);
            float4 v1 = make_float4(acc[ia][4], acc[ia][5], acc[ia][6], acc[ia][7]);
            *reinterpret_cast<float4*>(&g_y[m * COUT + n0 + bc0])      = v0;
            *reinterpret_cast<float4*>(&g_y[m * COUT + n0 + 64 + bc0]) = v1;
        }
    }

    // ---- fused BN partial stats for this (M-tile, 128 channels)
    __syncthreads();   // done reading As/Ws smem; safe to reuse
    float* sred = &As[0][0][0];   // [16][128] = 2048 floats (fits in As)
    float* qred = &Ws[0][0][0];   // [16][128]

    float s8[8], q8[8];
#pragma unroll
    for (int j = 0; j < 8; j++) { s8[j] = 0.0f; q8[j] = 0.0f; }
#pragma unroll
    for (int i = 0; i < 8; i++)
#pragma unroll
        for (int j = 0; j < 8; j++) {
            float v = acc[i][j];
            s8[j] += v;
            q8[j] = fmaf(v, v, q8[j]);
        }
#pragma unroll
    for (int jh = 0; jh < 2; jh++)
#pragma unroll
        for (int j = 0; j < 4; j++) {
            int c = jh * 64 + bc0 + j;         // CTA-local col 0..127
            sred[ty * 128 + c] = s8[jh * 4 + j];
            qred[ty * 128 + c] = q8[jh * 4 + j];
        }
    __syncthreads();

    if (tid < 128) {
        float s = 0.0f, q = 0.0f;
#pragma unroll
        for (int k = 0; k < 16; k++) {
            s += sred[k * 128 + tid];
            q += qred[k * 128 + tid];
        }
        g_psum[(size_t)blockIdx.y * COUT + n0 + tid] = s;
        g_psq [(size_t)blockIdx.y * COUT + n0 + tid] = q;
    }
}

// Finalize mean / rstd per channel (1 block, 512 threads)
__global__ void __launch_bounds__(COUT)
stats2_k() {
    const int o = threadIdx.x;
    float s = 0.0f, sq = 0.0f;
    for (int i = 0; i < NPART; i++) {
        s  += g_psum[i * COUT + o];
        sq += g_psq [i * COUT + o];
    }
    const float inv_m = 1.0f / (float)M_TOTAL;
    float mean = s * inv_m;
    float var  = sq * inv_m - mean * mean;
    g_mean[o] = mean;
    g_rstd[o] = rsqrtf(var + 1e-5f);
}

// ---------------------------------------------------------------------------
// Fused BN + multistep LIF + output store (HBM-bound; unchanged).
// ---------------------------------------------------------------------------
__global__ void __launch_bounds__(256)
lif_k(const float* __restrict__ gamma, const float* __restrict__ beta,
      float* __restrict__ out) {
    const int idx = blockIdx.x * blockDim.x + threadIdx.x;  // (b*N+n)*COUT + o
    const int total = B_BATCH * N_SEQ * COUT;
    if (idx >= total) return;
    const int o = idx & (COUT - 1);

    const float mean = g_mean[o];
    const float rstd = g_rstd[o];
    const float ga = gamma[o];
    const float be = beta[o];

    const size_t stride = (size_t)B_BATCH * N_SEQ * COUT;   // per-timestep stride
    const size_t base = (size_t)idx;

    float v = 0.0f;
#pragma unroll
    for (int t = 0; t < T_STEPS; t++) {
        const size_t off = base + (size_t)t * stride;
        float raw = g_y[off];
        float xt = (raw - mean) * rstd;
        xt = xt * ga + be;
        float d = xt - v;
        v = v + d * 0.5f;
        float sp = (v >= 1.0f) ? 1.0f : 0.0f;
        out[off] = sp;
        v = v * (1.0f - sp);
    }
}

// ---------------------------------------------------------------------------
extern "C" void kernel_launch(void* const* d_in, const int* in_sizes, int n_in,
                              void* d_out, int out_size) {
    const float* x     = (const float*)d_in[0];  // [TB, N, Cin] = [M_TOTAL, CIN]
    const float* W     = (const float*)d_in[1];  // [COUT, CIN]
    const float* gamma = (const float*)d_in[2];
    const float* beta  = (const float*)d_in[3];
    float* out = (float*)d_out;

    dim3 gemm_grid(COUT / BNb, M_TOTAL / BM);    // (4, 1024)
    gemm_k<<<gemm_grid, 256>>>(x, W);

    stats2_k<<<1, COUT>>>();

    const int total = B_BATCH * N_SEQ * COUT;    // 16.7M elements
    lif_k<<<(total + 255) / 256, 256>>>(gamma, beta, out);
}

// round 6
// speedup vs baseline: 1.3805x; 1.1153x over previous
#include <cuda_runtime.h>
#include <cstdint>

// Problem constants (fixed shapes from reference setup_inputs)
#define T_STEPS 4
#define B_BATCH 32            // TB / T = 128/4
#define N_SEQ   1024
#define CIN     512
#define COUT    512
#define M_TOTAL (T_STEPS * B_BATCH * N_SEQ)   // 131072 rows

// Scratch in device globals (no allocations allowed)
__device__ float g_y[(size_t)M_TOTAL * COUT];      // 268 MB GEMM output
#define NPART 1024                                  // one partial per M-tile
__device__ float g_psum[NPART * COUT];
__device__ float g_psq [NPART * COUT];
__device__ float g_mean[COUT];
__device__ float g_rstd[COUT];

// ---------------------------------------------------------------------------
// Packed f32x2 helpers. fma.rn.f32x2 = two independent fp32 rn FMAs on a
// 64-bit register pair -> bitwise-identical per-lane results to scalar fmaf.
// ---------------------------------------------------------------------------
__device__ __forceinline__ unsigned long long pack_dup(float a) {
    unsigned long long u;
    asm("mov.b64 %0, {%1, %1};" : "=l"(u) : "f"(a));
    return u;
}
__device__ __forceinline__ void fma2(unsigned long long& acc,
                                     unsigned long long a,
                                     unsigned long long b) {
    asm("fma.rn.f32x2 %0, %1, %2, %0;" : "+l"(acc) : "l"(a), "l"(b));
}
__device__ __forceinline__ float2 unpack2(unsigned long long u) {
    float lo, hi;
    asm("mov.b64 {%0, %1}, %2;" : "=f"(lo), "=f"(hi) : "l"(u));
    return make_float2(lo, hi);
}

// ---------------------------------------------------------------------------
// SGEMM: C[m,o] = sum_k A[m,k] * W[o,k], k accumulated sequentially in fp32
// (must match reference rounding pattern exactly; tensor cores change the
// accumulation tree and flip near-threshold spikes).
// 128x128x16 tile, 256 threads, 8x8 per thread (4+4 clustered rows/cols),
// double-buffered smem, inner product via packed fma.rn.f32x2 (2 cols/op).
// Epilogue emits per-(M-tile, channel) BN partial sums (deterministic tree).
// ---------------------------------------------------------------------------
#define BM 128
#define BNb 128
#define BK 16
#define SPAD 4

__global__ void __launch_bounds__(256, 2)
gemm_k(const float* __restrict__ A, const float* __restrict__ W) {
    __shared__ float As[2][BK][BM + SPAD];
    __shared__ float Ws[2][BK][BNb + SPAD];

    const int tid = threadIdx.x;
    const int tx = tid & 15;       // 0..15
    const int ty = tid >> 4;       // 0..15
    const int m0 = blockIdx.y * BM;
    const int n0 = blockIdx.x * BNb;

    const int ar0 = ty * 4;        // rows ar0..+3 and 64+ar0..+3
    const int bc0 = tx * 4;        // cols bc0..+3 and 64+bc0..+3

    // global load indices (per stage: 2 float4 for A, 2 for W)
    const int lrow0 = tid >> 2;          // 0..63
    const int lkv   = (tid & 3) * 4;     // 0,4,8,12

    const float* Aptr0 = A + (size_t)(m0 + lrow0) * CIN + lkv;
    const float* Wptr0 = W + (size_t)(n0 + lrow0) * CIN + lkv;
    const size_t row64 = (size_t)64 * CIN;

    // acc[i][jp]: row cluster i (0..7), col pair jp (0..3) = cols 2jp,2jp+1
    unsigned long long acc[8][4];
#pragma unroll
    for (int i = 0; i < 8; i++)
#pragma unroll
        for (int j = 0; j < 4; j++) acc[i][j] = 0ULL;

    // ---- prologue: load stage 0 into smem buffer 0
    {
        float4 ra0 = *reinterpret_cast<const float4*>(Aptr0);
        float4 ra1 = *reinterpret_cast<const float4*>(Aptr0 + row64);
        float4 rw0 = *reinterpret_cast<const float4*>(Wptr0);
        float4 rw1 = *reinterpret_cast<const float4*>(Wptr0 + row64);
        As[0][lkv + 0][lrow0] = ra0.x; As[0][lkv + 1][lrow0] = ra0.y;
        As[0][lkv + 2][lrow0] = ra0.z; As[0][lkv + 3][lrow0] = ra0.w;
        As[0][lkv + 0][lrow0 + 64] = ra1.x; As[0][lkv + 1][lrow0 + 64] = ra1.y;
        As[0][lkv + 2][lrow0 + 64] = ra1.z; As[0][lkv + 3][lrow0 + 64] = ra1.w;
        Ws[0][lkv + 0][lrow0] = rw0.x; Ws[0][lkv + 1][lrow0] = rw0.y;
        Ws[0][lkv + 2][lrow0] = rw0.z; Ws[0][lkv + 3][lrow0] = rw0.w;
        Ws[0][lkv + 0][lrow0 + 64] = rw1.x; Ws[0][lkv + 1][lrow0 + 64] = rw1.y;
        Ws[0][lkv + 2][lrow0 + 64] = rw1.z; Ws[0][lkv + 3][lrow0 + 64] = rw1.w;
    }
    __syncthreads();

    const int NSTAGE = CIN / BK;   // 32
    float4 ra0, ra1, rw0, rw1;

#pragma unroll 1
    for (int s = 0; s < NSTAGE; s++) {
        const int cur = s & 1;
        const int nxt = cur ^ 1;

        // issue global loads for next stage (latency hidden by compute)
        if (s + 1 < NSTAGE) {
            const int koff = (s + 1) * BK;
            ra0 = *reinterpret_cast<const float4*>(Aptr0 + koff);
            ra1 = *reinterpret_cast<const float4*>(Aptr0 + row64 + koff);
            rw0 = *reinterpret_cast<const float4*>(Wptr0 + koff);
            rw1 = *reinterpret_cast<const float4*>(Wptr0 + row64 + koff);
        }

        // compute current stage: per kk, 8 a-broadcast pairs, 4 b pairs x2,
        // 32 packed FMAs covering the 8x8 micro-tile.
#pragma unroll
        for (int kk = 0; kk < BK; kk++) {
            float4 a0 = *reinterpret_cast<const float4*>(&As[cur][kk][ar0]);
            float4 a1 = *reinterpret_cast<const float4*>(&As[cur][kk][ar0 + 64]);
            // b pairs: two float4 = 4 register pairs (lo = even col)
            float4 b0 = *reinterpret_cast<const float4*>(&Ws[cur][kk][bc0]);
            float4 b1 = *reinterpret_cast<const float4*>(&Ws[cur][kk][bc0 + 64]);
            unsigned long long bp[4];
            bp[0] = *reinterpret_cast<unsigned long long*>(&b0.x);
            bp[1] = *reinterpret_cast<unsigned long long*>(&b0.z);
            bp[2] = *reinterpret_cast<unsigned long long*>(&b1.x);
            bp[3] = *reinterpret_cast<unsigned long long*>(&b1.z);

            const float a[8] = {a0.x, a0.y, a0.z, a0.w, a1.x, a1.y, a1.z, a1.w};
#pragma unroll
            for (int i = 0; i < 8; i++) {
                const unsigned long long ap = pack_dup(a[i]);
#pragma unroll
                for (int jp = 0; jp < 4; jp++)
                    fma2(acc[i][jp], ap, bp[jp]);
            }
        }

        // stage next buffer
        if (s + 1 < NSTAGE) {
            As[nxt][lkv + 0][lrow0] = ra0.x; As[nxt][lkv + 1][lrow0] = ra0.y;
            As[nxt][lkv + 2][lrow0] = ra0.z; As[nxt][lkv + 3][lrow0] = ra0.w;
            As[nxt][lkv + 0][lrow0 + 64] = ra1.x; As[nxt][lkv + 1][lrow0 + 64] = ra1.y;
            As[nxt][lkv + 2][lrow0 + 64] = ra1.z; As[nxt][lkv + 3][lrow0 + 64] = ra1.w;
            Ws[nxt][lkv + 0][lrow0] = rw0.x; Ws[nxt][lkv + 1][lrow0] = rw0.y;
            Ws[nxt][lkv + 2][lrow0] = rw0.z; Ws[nxt][lkv + 3][lrow0] = rw0.w;
            Ws[nxt][lkv + 0][lrow0 + 64] = rw1.x; Ws[nxt][lkv + 1][lrow0 + 64] = rw1.y;
            Ws[nxt][lkv + 2][lrow0 + 64] = rw1.z; Ws[nxt][lkv + 3][lrow0 + 64] = rw1.w;
            __syncthreads();
        }
    }

    // unpack accumulators to scalar view acc_f[i][j] (j = col within cluster)
    float acc_f[8][8];
#pragma unroll
    for (int i = 0; i < 8; i++)
#pragma unroll
        for (int jp = 0; jp < 4; jp++) {
            float2 v = unpack2(acc[i][jp]);
            acc_f[i][2 * jp + 0] = v.x;
            acc_f[i][2 * jp + 1] = v.y;
        }

    // ---- store C tile (float4 per 4-col cluster)
#pragma unroll
    for (int ih = 0; ih < 2; ih++) {
#pragma unroll
        for (int i = 0; i < 4; i++) {
            const size_t m = (size_t)(m0 + ih * 64 + ar0 + i);
            const int ia = ih * 4 + i;
            float4 v0 = make_float4(acc_f[ia][0], acc_f[ia][1], acc_f[ia][2], acc_f[ia][3]);
            float4 v1 = make_float4(acc_f[ia][4], acc_f[ia][5], acc_f[ia][6], acc_f[ia][7]);
            *reinterpret_cast<float4*>(&g_y[m * COUT + n0 + bc0])      = v0;
            *reinterpret_cast<float4*>(&g_y[m * COUT + n0 + 64 + bc0]) = v1;
        }
    }

    // ---- fused BN partial stats for this (M-tile, 128 channels)
    __syncthreads();   // done reading As/Ws smem; safe to reuse
    float* sred = &As[0][0][0];   // [16][128]
    float* qred = &Ws[0][0][0];   // [16][128]

    float s8[8], q8[8];
#pragma unroll
    for (int j = 0; j < 8; j++) { s8[j] = 0.0f; q8[j] = 0.0f; }
#pragma unroll
    for (int i = 0; i < 8; i++)
#pragma unroll
        for (int j = 0; j < 8; j++) {
            float v = acc_f[i][j];
            s8[j] += v;
            q8[j] = fmaf(v, v, q8[j]);
        }
#pragma unroll
    for (int jh = 0; jh < 2; jh++)
#pragma unroll
        for (int j = 0; j < 4; j++) {
            int c = jh * 64 + bc0 + j;         // CTA-local col 0..127
            sred[ty * 128 + c] = s8[jh * 4 + j];
            qred[ty * 128 + c] = q8[jh * 4 + j];
        }
    __syncthreads();

    if (tid < 128) {
        float s = 0.0f, q = 0.0f;
#pragma unroll
        for (int k = 0; k < 16; k++) {
            s += sred[k * 128 + tid];
            q += qred[k * 128 + tid];
        }
        g_psum[(size_t)blockIdx.y * COUT + n0 + tid] = s;
        g_psq [(size_t)blockIdx.y * COUT + n0 + tid] = q;
    }
}

// Finalize mean / rstd per channel (1 block, 512 threads)
__global__ void __launch_bounds__(COUT)
stats2_k() {
    const int o = threadIdx.x;
    float s = 0.0f, sq = 0.0f;
    for (int i = 0; i < NPART; i++) {
        s  += g_psum[i * COUT + o];
        sq += g_psq [i * COUT + o];
    }
    const float inv_m = 1.0f / (float)M_TOTAL;
    float mean = s * inv_m;
    float var  = sq * inv_m - mean * mean;
    g_mean[o] = mean;
    g_rstd[o] = rsqrtf(var + 1e-5f);
}

// ---------------------------------------------------------------------------
// Fused BN + multistep LIF + output store (HBM-bound).
// ---------------------------------------------------------------------------
__global__ void __launch_bounds__(256)
lif_k(const float* __restrict__ gamma, const float* __restrict__ beta,
      float* __restrict__ out) {
    const int idx = blockIdx.x * blockDim.x + threadIdx.x;
    const int total = B_BATCH * N_SEQ * COUT;
    if (idx >= total) return;
    const int o = idx & (COUT - 1);

    const float mean = g_mean[o];
    const float rstd = g_rstd[o];
    const float ga = gamma[o];
    const float be = beta[o];

    const size_t stride = (size_t)B_BATCH * N_SEQ * COUT;
    const size_t base = (size_t)idx;

    float v = 0.0f;
#pragma unroll
    for (int t = 0; t < T_STEPS; t++) {
        const size_t off = base + (size_t)t * stride;
        float raw = g_y[off];
        float xt = (raw - mean) * rstd;
        xt = xt * ga + be;
        float d = xt - v;
        v = v + d * 0.5f;
        float sp = (v >= 1.0f) ? 1.0f : 0.0f;
        out[off] = sp;
        v = v * (1.0f - sp);
    }
}

// ---------------------------------------------------------------------------
extern "C" void kernel_launch(void* const* d_in, const int* in_sizes, int n_in,
                              void* d_out, int out_size) {
    const float* x     = (const float*)d_in[0];
    const float* W     = (const float*)d_in[1];
    const float* gamma = (const float*)d_in[2];
    const float* beta  = (const float*)d_in[3];
    float* out = (float*)d_out;

    dim3 gemm_grid(COUT / BNb, M_TOTAL / BM);    // (4, 1024)
    gemm_k<<<gemm_grid, 256>>>(x, W);

    stats2_k<<<1, COUT>>>();

    const int total = B_BATCH * N_SEQ * COUT;
    lif_k<<<(total + 255) / 256, 256>>>(gamma, beta, out);
}

// round 7
// speedup vs baseline: 1.4147x; 1.0248x over previous
#include <cuda_runtime.h>
#include <cstdint>

// Problem constants (fixed shapes from reference setup_inputs)
#define T_STEPS 4
#define B_BATCH 32            // TB / T = 128/4
#define N_SEQ   1024
#define CIN     512
#define COUT    512
#define M_TOTAL (T_STEPS * B_BATCH * N_SEQ)   // 131072 rows

// Scratch in device globals (no allocations allowed)
__device__ float g_y[(size_t)M_TOTAL * COUT];      // 268 MB GEMM output
__device__ float g_wt[CIN][COUT];                   // W transposed: [k][o], 1 MB
#define NPART 1024                                  // one partial per M-tile
__device__ float g_psum[NPART * COUT];
__device__ float g_psq [NPART * COUT];
__device__ float g_mean[COUT];
__device__ float g_rstd[COUT];

// ---------------------------------------------------------------------------
// Packed f32x2 helpers. fma.rn.f32x2 = two independent fp32 rn FMAs on a
// 64-bit register pair -> bitwise-identical per-lane results to scalar fmaf.
// ---------------------------------------------------------------------------
__device__ __forceinline__ unsigned long long pack_dup(float a) {
    unsigned long long u;
    asm("mov.b64 %0, {%1, %1};" : "=l"(u) : "f"(a));
    return u;
}
__device__ __forceinline__ void fma2(unsigned long long& acc,
                                     unsigned long long a,
                                     unsigned long long b) {
    asm("fma.rn.f32x2 %0, %1, %2, %0;" : "+l"(acc) : "l"(a), "l"(b));
}
__device__ __forceinline__ float2 unpack2(unsigned long long u) {
    float lo, hi;
    asm("mov.b64 {%0, %1}, %2;" : "=f"(lo), "=f"(hi) : "l"(u));
    return make_float2(lo, hi);
}
__device__ __forceinline__ uint32_t smem_u32(const void* p) {
    uint32_t a;
    asm("{ .reg .u64 t; cvta.to.shared.u64 t, %1; cvt.u32.u64 %0, t; }" : "=r"(a) : "l"(p));
    return a;
}
__device__ __forceinline__ void cp_async16(uint32_t dst, const void* src) {
    asm volatile("cp.async.cg.shared.global [%0], [%1], 16;" :: "r"(dst), "l"(src) : "memory");
}

// ---------------------------------------------------------------------------
// Tiled transpose: g_wt[k][o] = W[o][k]. 512x512, 32x32 tiles, 16x16 blocks.
// ---------------------------------------------------------------------------
__global__ void __launch_bounds__(256)
wt_k(const float* __restrict__ W) {
    __shared__ float t[32][33];
    const int bo = blockIdx.x * 32;       // o tile base
    const int bk = blockIdx.y * 32;       // k tile base
    const int lx = threadIdx.x & 31;
    const int ly = threadIdx.x >> 5;      // 0..7
#pragma unroll
    for (int i = 0; i < 4; i++)
        t[ly + 8 * i][lx] = W[(size_t)(bo + ly + 8 * i) * CIN + bk + lx];
    __syncthreads();
#pragma unroll
    for (int i = 0; i < 4; i++)
        g_wt[bk + ly + 8 * i][bo + lx] = t[lx][ly + 8 * i];
}

// ---------------------------------------------------------------------------
// SGEMM: C[m,o] = sum_k A[m,k] * W[o,k], k accumulated sequentially in fp32
// (must match reference rounding pattern exactly; tensor cores change the
// accumulation tree and flip near-threshold spikes -> rel_err > 1e-3).
// 128x128x16 tile, 256 threads, 8x8 per thread, double-buffered smem.
// W tile fetched with cp.async from pre-transposed g_wt (no staging regs,
// no STS) — frees registers so ptxas can pipeline fragment LDS.
// A tile register-prefetched + transposed on store (unavoidable).
// Inner product via packed fma.rn.f32x2. BN partials fused in epilogue.
// ---------------------------------------------------------------------------
#define BM 128
#define BNb 128
#define BK 16
#define SPAD 4
#define WROW (BNb + SPAD)

__global__ void __launch_bounds__(256, 2)
gemm_k(const float* __restrict__ A) {
    __shared__ float As[2][BK][BM + SPAD];
    __shared__ float Ws[2][BK][WROW];

    const int tid = threadIdx.x;
    const int tx = tid & 15;       // 0..15
    const int ty = tid >> 4;       // 0..15
    const int m0 = blockIdx.y * BM;
    const int n0 = blockIdx.x * BNb;

    const int ar0 = ty * 4;        // rows ar0..+3 and 64+ar0..+3
    const int bc0 = tx * 4;        // cols bc0..+3 and 64+bc0..+3

    // A global-load mapping: 2 float4 per thread per stage
    const int lrow0 = tid >> 2;          // 0..63
    const int lkv   = (tid & 3) * 4;     // 0,4,8,12
    const float* Aptr0 = A + (size_t)(m0 + lrow0) * CIN + lkv;
    const size_t row64 = (size_t)64 * CIN;

    // W cp.async mapping: 2 chunks of 16B per thread per stage
    // chunk id 0..511: k = id>>5 (0..15), c4 = id&31 -> cols c4*4..+3
    const int wk0 = tid >> 5;            // chunk tid:    k = tid>>5 (0..7)
    const int wc0 = tid & 31;
    const int wk1 = wk0 + 8;             // chunk tid+256: k = 8..15
    const uint32_t ws_u = smem_u32(&Ws[0][0][0]);
    const float* wsrc0 = &g_wt[wk0][n0 + wc0 * 4];
    const float* wsrc1 = &g_wt[wk1][n0 + wc0 * 4];

    auto load_W = [&](int buf, int k0) {
        const uint32_t base = ws_u + (uint32_t)buf * (BK * WROW * 4);
        cp_async16(base + (wk0 * WROW + wc0 * 4) * 4, wsrc0 + (size_t)k0 * COUT);
        cp_async16(base + (wk1 * WROW + wc0 * 4) * 4, wsrc1 + (size_t)k0 * COUT);
        asm volatile("cp.async.commit_group;" ::: "memory");
    };

    // acc[i][jp]: row cluster i (0..7), col pair jp (0..3) = cols 2jp,2jp+1
    unsigned long long acc[8][4];
#pragma unroll
    for (int i = 0; i < 8; i++)
#pragma unroll
        for (int j = 0; j < 4; j++) acc[i][j] = 0ULL;

    // ---- prologue: stage 0
    {
        load_W(0, 0);
        float4 ra0 = *reinterpret_cast<const float4*>(Aptr0);
        float4 ra1 = *reinterpret_cast<const float4*>(Aptr0 + row64);
        As[0][lkv + 0][lrow0] = ra0.x; As[0][lkv + 1][lrow0] = ra0.y;
        As[0][lkv + 2][lrow0] = ra0.z; As[0][lkv + 3][lrow0] = ra0.w;
        As[0][lkv + 0][lrow0 + 64] = ra1.x; As[0][lkv + 1][lrow0 + 64] = ra1.y;
        As[0][lkv + 2][lrow0 + 64] = ra1.z; As[0][lkv + 3][lrow0 + 64] = ra1.w;
    }
    asm volatile("cp.async.wait_group 0;" ::: "memory");
    __syncthreads();

    const int NSTAGE = CIN / BK;   // 32
    float4 ra0, ra1;

#pragma unroll 1
    for (int s = 0; s < NSTAGE; s++) {
        const int cur = s & 1;
        const int nxt = cur ^ 1;

        // issue next-stage loads (W via cp.async, A into regs)
        if (s + 1 < NSTAGE) {
            const int koff = (s + 1) * BK;
            load_W(nxt, koff);
            ra0 = *reinterpret_cast<const float4*>(Aptr0 + koff);
            ra1 = *reinterpret_cast<const float4*>(Aptr0 + row64 + koff);
        }

        // compute current stage
#pragma unroll
        for (int kk = 0; kk < BK; kk++) {
            float4 a0 = *reinterpret_cast<const float4*>(&As[cur][kk][ar0]);
            float4 a1 = *reinterpret_cast<const float4*>(&As[cur][kk][ar0 + 64]);
            float4 b0 = *reinterpret_cast<const float4*>(&Ws[cur][kk][bc0]);
            float4 b1 = *reinterpret_cast<const float4*>(&Ws[cur][kk][bc0 + 64]);
            unsigned long long bp[4];
            bp[0] = *reinterpret_cast<unsigned long long*>(&b0.x);
            bp[1] = *reinterpret_cast<unsigned long long*>(&b0.z);
            bp[2] = *reinterpret_cast<unsigned long long*>(&b1.x);
            bp[3] = *reinterpret_cast<unsigned long long*>(&b1.z);

            const float a[8] = {a0.x, a0.y, a0.z, a0.w, a1.x, a1.y, a1.z, a1.w};
#pragma unroll
            for (int i = 0; i < 8; i++) {
                const unsigned long long ap = pack_dup(a[i]);
#pragma unroll
                for (int jp = 0; jp < 4; jp++)
                    fma2(acc[i][jp], ap, bp[jp]);
            }
        }

        // stage next A buffer, wait W arrivals, barrier
        if (s + 1 < NSTAGE) {
            As[nxt][lkv + 0][lrow0] = ra0.x; As[nxt][lkv + 1][lrow0] = ra0.y;
            As[nxt][lkv + 2][lrow0] = ra0.z; As[nxt][lkv + 3][lrow0] = ra0.w;
            As[nxt][lkv + 0][lrow0 + 64] = ra1.x; As[nxt][lkv + 1][lrow0 + 64] = ra1.y;
            As[nxt][lkv + 2][lrow0 + 64] = ra1.z; As[nxt][lkv + 3][lrow0 + 64] = ra1.w;
            asm volatile("cp.async.wait_group 0;" ::: "memory");
            __syncthreads();
        }
    }

    // unpack accumulators to scalar view
    float acc_f[8][8];
#pragma unroll
    for (int i = 0; i < 8; i++)
#pragma unroll
        for (int jp = 0; jp < 4; jp++) {
            float2 v = unpack2(acc[i][jp]);
            acc_f[i][2 * jp + 0] = v.x;
            acc_f[i][2 * jp + 1] = v.y;
        }

    // ---- store C tile
#pragma unroll
    for (int ih = 0; ih < 2; ih++) {
#pragma unroll
        for (int i = 0; i < 4; i++) {
            const size_t m = (size_t)(m0 + ih * 64 + ar0 + i);
            const int ia = ih * 4 + i;
            float4 v0 = make_float4(acc_f[ia][0], acc_f[ia][1], acc_f[ia][2], acc_f[ia][3]);
            float4 v1 = make_float4(acc_f[ia][4], acc_f[ia][5], acc_f[ia][6], acc_f[ia][7]);
            *reinterpret_cast<float4*>(&g_y[m * COUT + n0 + bc0])      = v0;
            *reinterpret_cast<float4*>(&g_y[m * COUT + n0 + 64 + bc0]) = v1;
        }
    }

    // ---- fused BN partial stats for this (M-tile, 128 channels)
    __syncthreads();   // done reading As/Ws smem; safe to reuse
    float* sred = &As[0][0][0];   // [16][128]
    float* qred = &As[1][0][0];   // [16][128]

    float s8[8], q8[8];
#pragma unroll
    for (int j = 0; j < 8; j++) { s8[j] = 0.0f; q8[j] = 0.0f; }
#pragma unroll
    for (int i = 0; i < 8; i++)
#pragma unroll
        for (int j = 0; j < 8; j++) {
            float v = acc_f[i][j];
            s8[j] += v;
            q8[j] = fmaf(v, v, q8[j]);
        }
#pragma unroll
    for (int jh = 0; jh < 2; jh++)
#pragma unroll
        for (int j = 0; j < 4; j++) {
            int c = jh * 64 + bc0 + j;         // CTA-local col 0..127
            sred[ty * 128 + c] = s8[jh * 4 + j];
            qred[ty * 128 + c] = q8[jh * 4 + j];
        }
    __syncthreads();

    if (tid < 128) {
        float s = 0.0f, q = 0.0f;
#pragma unroll
        for (int k = 0; k < 16; k++) {
            s += sred[k * 128 + tid];
            q += qred[k * 128 + tid];
        }
        g_psum[(size_t)blockIdx.y * COUT + n0 + tid] = s;
        g_psq [(size_t)blockIdx.y * COUT + n0 + tid] = q;
    }
}

// Finalize mean / rstd per channel (1 block, 512 threads)
__global__ void __launch_bounds__(COUT)
stats2_k() {
    const int o = threadIdx.x;
    float s = 0.0f, sq = 0.0f;
    for (int i = 0; i < NPART; i++) {
        s  += g_psum[i * COUT + o];
        sq += g_psq [i * COUT + o];
    }
    const float inv_m = 1.0f / (float)M_TOTAL;
    float mean = s * inv_m;
    float var  = sq * inv_m - mean * mean;
    g_mean[o] = mean;
    g_rstd[o] = rsqrtf(var + 1e-5f);
}

// ---------------------------------------------------------------------------
// Fused BN + multistep LIF + output store (HBM-bound).
// ---------------------------------------------------------------------------
__global__ void __launch_bounds__(256)
lif_k(const float* __restrict__ gamma, const float* __restrict__ beta,
      float* __restrict__ out) {
    const int idx = blockIdx.x * blockDim.x + threadIdx.x;
    const int total = B_BATCH * N_SEQ * COUT;
    if (idx >= total) return;
    const int o = idx & (COUT - 1);

    const float mean = g_mean[o];
    const float rstd = g_rstd[o];
    const float ga = gamma[o];
    const float be = beta[o];

    const size_t stride = (size_t)B_BATCH * N_SEQ * COUT;
    const size_t base = (size_t)idx;

    float v = 0.0f;
#pragma unroll
    for (int t = 0; t < T_STEPS; t++) {
        const size_t off = base + (size_t)t * stride;
        float raw = g_y[off];
        float xt = (raw - mean) * rstd;
        xt = xt * ga + be;
        float d = xt - v;
        v = v + d * 0.5f;
        float sp = (v >= 1.0f) ? 1.0f : 0.0f;
        out[off] = sp;
        v = v * (1.0f - sp);
    }
}

// ---------------------------------------------------------------------------
extern "C" void kernel_launch(void* const* d_in, const int* in_sizes, int n_in,
                              void* d_out, int out_size) {
    const float* x     = (const float*)d_in[0];
    const float* W     = (const float*)d_in[1];
    const float* gamma = (const float*)d_in[2];
    const float* beta  = (const float*)d_in[3];
    float* out = (float*)d_out;

    dim3 wt_grid(COUT / 32, CIN / 32);           // (16, 16)
    wt_k<<<wt_grid, 256>>>(W);

    dim3 gemm_grid(COUT / BNb, M_TOTAL / BM);    // (4, 1024)
    gemm_k<<<gemm_grid, 256>>>(x);

    stats2_k<<<1, COUT>>>();

    const int total = B_BATCH * N_SEQ * COUT;
    lif_k<<<(total + 255) / 256, 256>>>(gamma, beta, out);
}